// round 12
// baseline (speedup 1.0000x reference)
#include <cuda_runtime.h>
#include <cstdint>

// Fixed shapes: points (4, 8192, 3) fp32
#define BATCH     4
#define NPTS      8192
#define NTOT      (BATCH * NPTS)
#define NN_SIZE   16
#define RADIUS2   0.25f
#define EPS_LOSS  1e-4f

// Spatial grid: cell width 0.5 (= radius), domain [-5,5) clamped
#define GDIM      20
#define NCELLS    (GDIM * GDIM * GDIM)     // 8000
#define GMIN      (-5.0f)
#define INV_CW    2.0f
#define CW        0.5f

// Main kernel layout
#define SPLIT     4
#define TPB       128
#define QPB       (TPB / SPLIT)            // 32 queries per block
#define BPB       (NPTS / QPB)             // 256 blocks per batch
#define NBLK      (BATCH * BPB)            // 1024
#define MROW      65                       // conflict-free merge-row stride

// Scan kernel layout
#define SCAN_T    256
#define CPT       32                       // 256*32 = 8192 >= 8000

// All zero at module load; self-restored every run for graph replay.
__device__ int      g_count [BATCH * NCELLS];
__device__ int      g_start [BATCH * NCELLS];  // excl prefix; becomes END after scatter
__device__ float4   g_sorted[NTOT + 16];       // +pad for unconditional paired loads
__device__ int      g_sid   [NTOT];            // sorted pos -> original index
__device__ float    g_loss  [NTOT];            // per ORIGINAL index (deterministic)
__device__ unsigned g_done;                    // k_main completion ticket

__device__ __forceinline__ int cell_of(float x, float y, float z) {
    int cx = (int)floorf((x - GMIN) * INV_CW);
    int cy = (int)floorf((y - GMIN) * INV_CW);
    int cz = (int)floorf((z - GMIN) * INV_CW);
    cx = min(max(cx, 0), GDIM - 1);
    cy = min(max(cy, 0), GDIM - 1);
    cz = min(max(cz, 0), GDIM - 1);
    return (cz * GDIM + cy) * GDIM + cx;
}

__global__ void k_count(const float* __restrict__ pts) {
    int i = blockIdx.x * blockDim.x + threadIdx.x;
    if (i >= NTOT) return;
    int b = i >> 13;
    float x = pts[3 * i + 0], y = pts[3 * i + 1], z = pts[3 * i + 2];
    atomicAdd(&g_count[b * NCELLS + cell_of(x, y, z)], 1);
}

// Register-blocked exclusive scan per batch; self-zeroes g_count after reading.
__global__ __launch_bounds__(SCAN_T) void k_scan() {
    __shared__ int wsum[SCAN_T / 32];
    const int b = blockIdx.x;
    const int t = threadIdx.x;
    const int lane = t & 31, warp = t >> 5;
    const int base = t * CPT;

    int v[CPT];
    int tot = 0;
#pragma unroll
    for (int i = 0; i < CPT; ++i) {
        int c = base + i;
        v[i] = (c < NCELLS) ? g_count[b * NCELLS + c] : 0;
        tot += v[i];
    }
    int inc = tot;
#pragma unroll
    for (int off = 1; off < 32; off <<= 1) {
        int n = __shfl_up_sync(0xffffffffu, inc, off);
        if (lane >= off) inc += n;
    }
    if (lane == 31) wsum[warp] = inc;
    __syncthreads();
    if (warp == 0 && lane < SCAN_T / 32) {
        int w = wsum[lane];
#pragma unroll
        for (int off = 1; off < SCAN_T / 32; off <<= 1) {
            int n = __shfl_up_sync(0xffu, w, off);
            if (lane >= off) w += n;
        }
        wsum[lane] = w;
    }
    __syncthreads();
    int excl = inc - tot + (warp ? wsum[warp - 1] : 0);
#pragma unroll
    for (int i = 0; i < CPT; ++i) {
        int c = base + i;
        if (c < NCELLS) {
            g_start[b * NCELLS + c] = excl;
            g_count[b * NCELLS + c] = 0;   // self-restore for next replay
        }
        excl += v[i];
    }
}

// Scatter; atomic consume of g_start turns it into the END-offset array.
__global__ void k_scatter(const float* __restrict__ pts) {
    int i = blockIdx.x * blockDim.x + threadIdx.x;
    if (i >= NTOT) return;
    int b = i >> 13;
    float x = pts[3 * i + 0], y = pts[3 * i + 1], z = pts[3 * i + 2];
    int c = cell_of(x, y, z);
    int pos = atomicAdd(&g_start[b * NCELLS + c], 1);
    float w = 0.5f * (x * x + y * y + z * z);
    g_sorted[b * NPTS + pos] = make_float4(x, y, z, w);
    g_sid[b * NPTS + pos] = i - b * NPTS;
}

// Branchless sorted insert (ascending), drop a[15].
__device__ __forceinline__ void sorted_insert16(float (&a)[16], float v) {
#pragma unroll
    for (int k = 15; k > 0; --k) {
        a[k] = fminf(fmaxf(v, a[k - 1]), a[k]);
    }
    a[0] = fminf(a[0], v);
}

// 2x-unrolled run scan (paired independent loads; g_sorted padded).
template <bool SELF>
__device__ __forceinline__ void scan_run(const float4* __restrict__ spts,
                                         int k0, int k1, int s, int g,
                                         float nqx, float nqy, float nqz,
                                         float (&a)[16]) {
    int k = k0 + s;
    for (; k + SPLIT < k1; k += 2 * SPLIT) {
        float4 c0 = spts[k];
        float4 c1 = spts[k + SPLIT];          // in-bounds of padded array
        float e0 = fmaf(c0.x, nqx, fmaf(c0.y, nqy, fmaf(c0.z, nqz, c0.w)));
        float e1 = fmaf(c1.x, nqx, fmaf(c1.y, nqy, fmaf(c1.z, nqz, c1.w)));
        bool ok0 = e0 < a[15], ok1 = e1 < a[15];
        if (SELF) { ok0 = ok0 && (k != g); ok1 = ok1 && (k + SPLIT != g); }
        if (ok0) sorted_insert16(a, e0);
        if (ok1) sorted_insert16(a, e1);
    }
    if (k < k1) {
        float4 c0 = spts[k];
        float e0 = fmaf(c0.x, nqx, fmaf(c0.y, nqy, fmaf(c0.z, nqz, c0.w)));
        bool ok0 = e0 < a[15];
        if (SELF) ok0 = ok0 && (k != g);
        if (ok0) sorted_insert16(a, e0);
    }
}

__global__ __launch_bounds__(TPB) void k_main(float* __restrict__ out) {
    __shared__ float mbuf[QPB * MROW];     // 8.3 KB
    __shared__ float qw_s[QPB];
    __shared__ int   last_s;

    const int t  = threadIdx.x;
    const int ql = t >> 2;                  // local query 0..31
    const int s  = t & 3;                   // split lane 0..3
    const int b  = blockIdx.x / BPB;
    // Heavy-first: dense (cloud-center) queries sit in the middle of sorted
    // order; launch them first to shrink the tail wave.
    const int i  = blockIdx.x % BPB;
    const int blkq = (i & 1) ? (BPB / 2 + (i >> 1)) : (BPB / 2 - 1 - (i >> 1));
    const int g  = blkq * QPB + ql;         // sorted query position

    const float4* __restrict__ spts = &g_sorted[b * NPTS];
    const int*    __restrict__ cend = &g_start[b * NCELLS];

    const float4 qp = spts[g];
    const float nqx = -qp.x, nqy = -qp.y, nqz = -qp.z;
    const float ecap = 0.5f * RADIUS2 - qp.w;       // e < ecap  <=>  d^2 < R^2
    if (s == 0) qw_s[ql] = qp.w;

    int cx = (int)floorf((qp.x - GMIN) * INV_CW);
    int cy = (int)floorf((qp.y - GMIN) * INV_CW);
    int cz = (int)floorf((qp.z - GMIN) * INV_CW);
    cx = min(max(cx, 0), GDIM - 1);
    cy = min(max(cy, 0), GDIM - 1);
    cz = min(max(cz, 0), GDIM - 1);

    // ---- Collect all candidate row-ranges first (independent cend loads ->
    //      MLP covers L2 latency once). Center row (dz==dy==0) is index 0. ----
    int r0[9], r1[9];
    int nr = 0;
    {
        const int OZ[3] = {0, -1, 1};
#pragma unroll
        for (int jz = 0; jz < 3; ++jz) {
            int nz = cz + OZ[jz];
            if ((unsigned)nz >= GDIM) continue;
            float zlo = GMIN + (float)nz * CW;
            float zd  = fmaxf(0.0f, fmaxf(zlo - qp.z, qp.z - (zlo + CW)));
            float zd2 = zd * zd;
#pragma unroll
            for (int jy = 0; jy < 3; ++jy) {
                int ny = cy + OZ[jy];
                if ((unsigned)ny >= GDIM) continue;
                float ylo = GMIN + (float)ny * CW;
                float yd  = fmaxf(0.0f, fmaxf(ylo - qp.y, qp.y - (ylo + CW)));
                float yz2 = fmaf(yd, yd, zd2);
                if (yz2 >= RADIUS2 + 1e-5f) continue;      // exact row prune
                float xr = sqrtf(RADIUS2 - yz2) + 1e-3f;   // over-inclusive (safe)
                int xa = max((int)floorf((qp.x - xr - GMIN) * INV_CW), 0);
                int xb = min((int)floorf((qp.x + xr - GMIN) * INV_CW), GDIM - 1);
                if (xa > xb) continue;
                int row = (nz * GDIM + ny) * GDIM;
                int c0  = row + xa;
                r0[nr] = (c0 == 0) ? 0 : cend[c0 - 1];
                r1[nr] = cend[row + xb];
                ++nr;
            }
        }
    }

    // ---- Scan: center row (contains self) first, then the rest. ----
    float a[16];
#pragma unroll
    for (int k = 0; k < 16; ++k) a[k] = ecap;

    scan_run<true>(spts, r0[0], r1[0], s, g, nqx, nqy, nqz, a);
    for (int r = 1; r < nr; ++r) {
        scan_run<false>(spts, r0[r], r1[r], s, g, nqx, nqy, nqz, a);
    }

    // Dump 4 sorted 16-lists per query.
#pragma unroll
    for (int k = 0; k < 16; ++k) {
        mbuf[ql * MROW + (s << 4) + k] = a[k];
    }
    __syncthreads();

    // One thread per query: 16-step 4-way pointer merge, ascending-e order.
    if (t < QPB) {
        const float* L   = &mbuf[t * MROW];
        const float  w   = qw_s[t];
        const float  cap = 0.5f * RADIUS2 - w;
        float part = 0.0f;
        int p0 = 0, p1 = 16, p2 = 32, p3 = 48;
#pragma unroll 1
        for (int it = 0; it < NN_SIZE; ++it) {
            float h0 = L[p0], h1 = L[p1], h2 = L[p2], h3 = L[p3];
            float m = fminf(fminf(h0, h1), fminf(h2, h3));
            if (m >= cap) break;
            part += rsqrtf(fmaf(2.0f, w + m, EPS_LOSS));   // d^2 = 2*(w+e)
            if      (m == h0) ++p0;
            else if (m == h1) ++p1;
            else if (m == h2) ++p2;
            else              ++p3;
        }
        int oid = g_sid[b * NPTS + blkq * QPB + t];
        g_loss[b * NPTS + oid] = part;
    }

    // Last-block fixed-order final reduction (deterministic; saves a launch).
    __threadfence();
    __syncthreads();
    if (t == 0) {
        unsigned ticket = atomicAdd(&g_done, 1u);
        last_s = (ticket == NBLK - 1) ? 1 : 0;
    }
    __syncthreads();
    if (last_s) {
        __shared__ float r[TPB];
        float sum = 0.0f;
#pragma unroll
        for (int j = 0; j < NTOT / TPB; ++j) {
            sum += g_loss[j * TPB + t];
        }
        r[t] = sum;
        __syncthreads();
#pragma unroll
        for (int off = TPB / 2; off > 0; off >>= 1) {
            if (t < off) r[t] += r[t + off];
            __syncthreads();
        }
        if (t == 0) {
            out[0] = r[0] * (1.0f / (float)(NTOT * NN_SIZE));
            g_done = 0;                     // self-restore for next replay
        }
    }
}

extern "C" void kernel_launch(void* const* d_in, const int* in_sizes, int n_in,
                              void* d_out, int out_size) {
    (void)in_sizes; (void)n_in; (void)out_size;
    const float* pts = (const float*)d_in[0];
    float* out = (float*)d_out;

    k_count  <<<(NTOT + 255) / 256, 256>>>(pts);   // idx 0
    k_scan   <<<BATCH, SCAN_T>>>();                // idx 1
    k_scatter<<<(NTOT + 255) / 256, 256>>>(pts);   // idx 2
    k_main   <<<NBLK, TPB>>>(out);                 // idx 3  <- ncu -s 5 lands here
}

// round 15
// speedup vs baseline: 1.3298x; 1.3298x over previous
#include <cuda_runtime.h>
#include <cstdint>

// Fixed shapes: points (4, 8192, 3) fp32
#define BATCH     4
#define NPTS      8192
#define NTOT      (BATCH * NPTS)
#define NN_SIZE   16
#define RADIUS2   0.25f
#define EPS_LOSS  1e-4f

// Spatial grid: cell width 0.25, domain [-5,5) clamped
#define GDIM      40
#define NCELLS    (GDIM * GDIM * GDIM)     // 64000 per batch
#define GMIN      (-5.0f)
#define INV_CW    4.0f
#define CW        0.25f

// Hierarchical scan: 256 segments x 250 cells per batch
#define NSEG      256
#define SEGC      (NCELLS / NSEG)          // 250
#define SCAN_T    128
#define SCAN_W    (SCAN_T / 32)            // 4 warps
#define SCAN_WMASK ((1u << SCAN_W) - 1u)   // 0xF — matches participating lanes!

// Main kernel layout
#define SPLIT     4
#define TPB       128
#define QPB       (TPB / SPLIT)            // 32 queries per block
#define BPB       (NPTS / QPB)             // 256 blocks per batch
#define NBLK      (BATCH * BPB)            // 1024
#define MROW      65                       // conflict-free merge-row stride

// All zero at module load; self-restored every run for graph replay.
__device__ int      g_count [BATCH * NCELLS];
__device__ int      g_start [BATCH * NCELLS];  // excl prefix; becomes END after scatter
__device__ int      g_part  [BATCH * NSEG];    // segment totals -> excl offsets
__device__ float4   g_sorted[NTOT + 16];       // +pad
__device__ int      g_sid   [NTOT];            // sorted pos -> original index
__device__ float    g_loss  [NTOT];            // per ORIGINAL index (deterministic)
__device__ unsigned g_done;                    // k_main completion ticket

__device__ __forceinline__ int cell_of(float x, float y, float z) {
    int cx = (int)floorf((x - GMIN) * INV_CW);
    int cy = (int)floorf((y - GMIN) * INV_CW);
    int cz = (int)floorf((z - GMIN) * INV_CW);
    cx = min(max(cx, 0), GDIM - 1);
    cy = min(max(cy, 0), GDIM - 1);
    cz = min(max(cz, 0), GDIM - 1);
    return (cz * GDIM + cy) * GDIM + cx;
}

__global__ void k_count(const float* __restrict__ pts) {
    int i = blockIdx.x * blockDim.x + threadIdx.x;
    if (i >= NTOT) return;
    int b = i >> 13;
    float x = pts[3 * i + 0], y = pts[3 * i + 1], z = pts[3 * i + 2];
    atomicAdd(&g_count[b * NCELLS + cell_of(x, y, z)], 1);
}

// Segment totals: one block per (batch, segment); 1024 blocks.
__global__ __launch_bounds__(SCAN_T) void k_scanA() {
    __shared__ int red[SCAN_T];
    const int blk = blockIdx.x;
    const int t   = threadIdx.x;
    const int base = (blk / NSEG) * NCELLS + (blk % NSEG) * SEGC;
    int s = 0;
    for (int i = t; i < SEGC; i += SCAN_T) s += g_count[base + i];
    red[t] = s;
    __syncthreads();
#pragma unroll
    for (int off = SCAN_T / 2; off > 0; off >>= 1) {
        if (t < off) red[t] += red[t + off];
        __syncthreads();
    }
    if (t == 0) g_part[blk] = red[0];
}

// Per-batch exclusive scan of 256 segment totals (one block per batch).
// 8 warps -> 8 participating lanes in the cross-warp scan; mask 0xFF correct.
__global__ __launch_bounds__(256) void k_scanB() {
    __shared__ int wsum[8];
    const int b = blockIdx.x;
    const int t = threadIdx.x;
    const int lane = t & 31, warp = t >> 5;
    int v = g_part[b * NSEG + t];
    int inc = v;
#pragma unroll
    for (int off = 1; off < 32; off <<= 1) {
        int n = __shfl_up_sync(0xffffffffu, inc, off);
        if (lane >= off) inc += n;
    }
    if (lane == 31) wsum[warp] = inc;
    __syncthreads();
    if (warp == 0 && lane < 8) {
        int w = wsum[lane];
#pragma unroll
        for (int off = 1; off < 8; off <<= 1) {
            int n = __shfl_up_sync(0xffu, w, off);
            if (lane >= off) w += n;
        }
        wsum[lane] = w;
    }
    __syncthreads();
    g_part[b * NSEG + t] = inc - v + (warp ? wsum[warp - 1] : 0);
}

// Local exclusive scan per segment + global offset; self-zeroes g_count.
// FIX vs R13/R14: cross-warp shfl mask now SCAN_WMASK (0xF) matching the
// SCAN_W=4 participating lanes — mask 0xFF named lanes that never arrive -> hang.
__global__ __launch_bounds__(SCAN_T) void k_scanC() {
    __shared__ int wsum[SCAN_W];
    const int blk = blockIdx.x;
    const int t   = threadIdx.x;
    const int lane = t & 31, warp = t >> 5;
    const int base = (blk / NSEG) * NCELLS + (blk % NSEG) * SEGC;
    const int goff = g_part[blk];

    // 2 cells per thread (128*2 = 256 >= 250)
    int v0 = (2 * t     < SEGC) ? g_count[base + 2 * t]     : 0;
    int v1 = (2 * t + 1 < SEGC) ? g_count[base + 2 * t + 1] : 0;
    int tot = v0 + v1;
    int inc = tot;
#pragma unroll
    for (int off = 1; off < 32; off <<= 1) {
        int n = __shfl_up_sync(0xffffffffu, inc, off);
        if (lane >= off) inc += n;
    }
    if (lane == 31) wsum[warp] = inc;
    __syncthreads();
    if (warp == 0 && lane < SCAN_W) {
        int w = wsum[lane];
#pragma unroll
        for (int off = 1; off < SCAN_W; off <<= 1) {
            int n = __shfl_up_sync(SCAN_WMASK, w, off);
            if (lane >= off) w += n;
        }
        wsum[lane] = w;
    }
    __syncthreads();
    int excl = goff + inc - tot + (warp ? wsum[warp - 1] : 0);
    if (2 * t < SEGC) {
        g_start[base + 2 * t] = excl;
        g_count[base + 2 * t] = 0;
    }
    if (2 * t + 1 < SEGC) {
        g_start[base + 2 * t + 1] = excl + v0;
        g_count[base + 2 * t + 1] = 0;
    }
}

// Scatter; atomic consume of g_start turns it into the END-offset array.
__global__ void k_scatter(const float* __restrict__ pts) {
    int i = blockIdx.x * blockDim.x + threadIdx.x;
    if (i >= NTOT) return;
    int b = i >> 13;
    float x = pts[3 * i + 0], y = pts[3 * i + 1], z = pts[3 * i + 2];
    int c = cell_of(x, y, z);
    int pos = atomicAdd(&g_start[b * NCELLS + c], 1);
    float w = 0.5f * (x * x + y * y + z * z);
    g_sorted[b * NPTS + pos] = make_float4(x, y, z, w);
    g_sid[b * NPTS + pos] = i - b * NPTS;
}

// Branchless sorted insert (ascending), drop a[15].
__device__ __forceinline__ void sorted_insert16(float (&a)[16], float v) {
#pragma unroll
    for (int k = 15; k > 0; --k) {
        a[k] = fminf(fmaxf(v, a[k - 1]), a[k]);
    }
    a[0] = fminf(a[0], v);
}

// 2x-unrolled run scan: paired independent loads.
__device__ __forceinline__ void scan_run(const float4* __restrict__ spts,
                                         int k0, int k1, int s, int g,
                                         float nqx, float nqy, float nqz,
                                         float (&a)[16]) {
    int k = k0 + s;
    for (; k + SPLIT < k1; k += 2 * SPLIT) {
        float4 c0 = spts[k];
        float4 c1 = spts[k + SPLIT];
        float e0 = fmaf(c0.x, nqx, fmaf(c0.y, nqy, fmaf(c0.z, nqz, c0.w)));
        float e1 = fmaf(c1.x, nqx, fmaf(c1.y, nqy, fmaf(c1.z, nqz, c1.w)));
        if (e0 < a[15] && k != g) sorted_insert16(a, e0);
        if (e1 < a[15] && (k + SPLIT) != g) sorted_insert16(a, e1);
    }
    if (k < k1) {
        float4 c0 = spts[k];
        float e0 = fmaf(c0.x, nqx, fmaf(c0.y, nqy, fmaf(c0.z, nqz, c0.w)));
        if (e0 < a[15] && k != g) sorted_insert16(a, e0);
    }
}

__global__ __launch_bounds__(TPB) void k_main(float* __restrict__ out) {
    __shared__ float mbuf[QPB * MROW];     // 8.3 KB
    __shared__ float qw_s[QPB];
    __shared__ int   last_s;

    const int t  = threadIdx.x;
    const int ql = t >> 2;                  // local query 0..31
    const int s  = t & 3;                   // split lane 0..3
    const int b  = blockIdx.x / BPB;
    // Heavy-first: dense (cloud-center) queries sit mid-sorted-order.
    const int i  = blockIdx.x % BPB;
    const int blkq = (i & 1) ? (BPB / 2 + (i >> 1)) : (BPB / 2 - 1 - (i >> 1));
    const int g  = blkq * QPB + ql;         // sorted query position

    const float4* __restrict__ spts = &g_sorted[b * NPTS];
    const int*    __restrict__ cend = &g_start[b * NCELLS];

    const float4 qp = spts[g];
    const float nqx = -qp.x, nqy = -qp.y, nqz = -qp.z;
    const float ecap = 0.5f * RADIUS2 - qp.w;       // e < ecap  <=>  d^2 < R^2
    if (s == 0) qw_s[ql] = qp.w;

    float a[16];
#pragma unroll
    for (int k = 0; k < 16; ++k) a[k] = ecap;

    int cx = (int)floorf((qp.x - GMIN) * INV_CW);
    int cy = (int)floorf((qp.y - GMIN) * INV_CW);
    int cz = (int)floorf((qp.z - GMIN) * INV_CW);
    cx = min(max(cx, 0), GDIM - 1);
    cy = min(max(cy, 0), GDIM - 1);
    cz = min(max(cz, 0), GDIM - 1);

    const int ORD[5] = {0, -1, 1, -2, 2};   // closest planes/rows first

#pragma unroll 1
    for (int jz = 0; jz < 5; ++jz) {
        int nz = cz + ORD[jz];
        if ((unsigned)nz >= GDIM) continue;
        float zlo = GMIN + (float)nz * CW;
        float zd  = fmaxf(0.0f, fmaxf(zlo - qp.z, qp.z - (zlo + CW)));
        float zd2 = zd * zd;
        if (zd2 >= RADIUS2 + 1e-5f) continue;

        // Prefetch all 5 row-ranges of this plane (static indices -> registers;
        // up to 10 independent cend loads in flight).
        int ka[5], kb[5];
#pragma unroll
        for (int jy = 0; jy < 5; ++jy) {
            int ny = cy + ORD[jy];
            bool ok = ((unsigned)ny < GDIM);
            float ylo = GMIN + (float)ny * CW;
            float yd  = fmaxf(0.0f, fmaxf(ylo - qp.y, qp.y - (ylo + CW)));
            float yz2 = fmaf(yd, yd, zd2);
            ok = ok && (yz2 < RADIUS2 + 1e-5f);      // exact row prune
            float xr = sqrtf(fmaxf(RADIUS2 - yz2, 0.0f)) + 1e-3f;  // over-incl. safe
            int xa = max((int)floorf((qp.x - xr - GMIN) * INV_CW), 0);
            int xb = min((int)floorf((qp.x + xr - GMIN) * INV_CW), GDIM - 1);
            ok = ok && (xa <= xb);
            int row = (nz * GDIM + ((unsigned)ny < GDIM ? ny : 0)) * GDIM;
            int c0  = row + xa;
            ka[jy] = ok ? ((c0 == 0) ? 0 : cend[c0 - 1]) : 0;
            kb[jy] = ok ? cend[row + xb] : 0;        // empty run when !ok
        }
#pragma unroll
        for (int jy = 0; jy < 5; ++jy) {
            scan_run(spts, ka[jy], kb[jy], s, g, nqx, nqy, nqz, a);
        }
    }

    // Dump 4 sorted 16-lists per query.
#pragma unroll
    for (int k = 0; k < 16; ++k) {
        mbuf[ql * MROW + (s << 4) + k] = a[k];
    }
    __syncthreads();

    // One thread per query: 16-step 4-way pointer merge, ascending-e order.
    if (t < QPB) {
        const float* L   = &mbuf[t * MROW];
        const float  w   = qw_s[t];
        const float  cap = 0.5f * RADIUS2 - w;
        float part = 0.0f;
        int p0 = 0, p1 = 16, p2 = 32, p3 = 48;
#pragma unroll 1
        for (int it = 0; it < NN_SIZE; ++it) {
            float h0 = L[p0], h1 = L[p1], h2 = L[p2], h3 = L[p3];
            float m = fminf(fminf(h0, h1), fminf(h2, h3));
            if (m >= cap) break;
            part += rsqrtf(fmaf(2.0f, w + m, EPS_LOSS));   // d^2 = 2*(w+e)
            if      (m == h0) ++p0;
            else if (m == h1) ++p1;
            else if (m == h2) ++p2;
            else              ++p3;
        }
        int oid = g_sid[b * NPTS + blkq * QPB + t];
        g_loss[b * NPTS + oid] = part;
    }

    // Last-block fixed-order final reduction (proven in R11/R12; no spinning).
    __threadfence();
    __syncthreads();
    if (t == 0) {
        unsigned ticket = atomicAdd(&g_done, 1u);
        last_s = (ticket == NBLK - 1) ? 1 : 0;
    }
    __syncthreads();
    if (last_s) {
        __shared__ float r[TPB];
        float sum = 0.0f;
#pragma unroll
        for (int j = 0; j < NTOT / TPB; ++j) {
            sum += g_loss[j * TPB + t];
        }
        r[t] = sum;
        __syncthreads();
#pragma unroll
        for (int off = TPB / 2; off > 0; off >>= 1) {
            if (t < off) r[t] += r[t + off];
            __syncthreads();
        }
        if (t == 0) {
            out[0] = r[0] * (1.0f / (float)(NTOT * NN_SIZE));
            g_done = 0;                     // self-restore for next replay
        }
    }
}

extern "C" void kernel_launch(void* const* d_in, const int* in_sizes, int n_in,
                              void* d_out, int out_size) {
    (void)in_sizes; (void)n_in; (void)out_size;
    const float* pts = (const float*)d_in[0];
    float* out = (float*)d_out;

    k_count  <<<(NTOT + 255) / 256, 256>>>(pts);   // idx 0
    k_scanA  <<<BATCH * NSEG, SCAN_T>>>();         // idx 1
    k_scanB  <<<BATCH, NSEG>>>();                  // idx 2
    k_scanC  <<<BATCH * NSEG, SCAN_T>>>();         // idx 3
    k_scatter<<<(NTOT + 255) / 256, 256>>>(pts);   // idx 4
    k_main   <<<NBLK, TPB>>>(out);                 // idx 5
}